// round 8
// baseline (speedup 1.0000x reference)
#include <cuda_runtime.h>
#include <cstdint>

// ---------------------------------------------------------------------------
// GIN block. 7-kernel pipeline:
//   init (dtype detect + zero)  -> hist -> single-pass lookback scan ->
//   permute -> gemm1 (CSR gather fused into A-tile load, mma.sync 3xTF32,
//   fused BN1 stats) -> gemm2 (BN1+ReLU folded, fused BN2 stats) -> bnrelu.
// NOTE: __device__ symbols must only be referenced from device code (R6 bug:
// host-side references bind the host shadow; ATS makes it silently "work").
// ---------------------------------------------------------------------------

#define MAXN 50048
#define MAXE 1600000

__device__ __align__(16) float g_h1[MAXN * 128];
__device__ float g_stats[512];   // [sum1, sumsq1, sum2, sumsq2] x 128
__device__ int   g_deg[MAXN + 1];
__device__ int   g_off[MAXN + 1];
__device__ int   g_pos[MAXN + 1];
__device__ unsigned long long g_look[64];  // lookback: flag(hi32) | value(lo32)
__device__ int   g_srcsorted[MAXE];
__device__ int   g_is64;

// ---------------------------------------------------------------------------
// init: zero histogram/stats/lookback; block 0 also detects edge dtype.
// int64 node ids < 2^31 -> every odd int32 word is zero; int32 edges -> not.
__global__ void init_kernel(const int* __restrict__ ei32, int E, int N) {
    int i = blockIdx.x * blockDim.x + threadIdx.x;
    if (i <= N) g_deg[i] = 0;
    if (i < 512) g_stats[i] = 0.f;
    if (i < 64) g_look[i] = 0ull;
    if (blockIdx.x == 0) {
        __shared__ int nz;
        if (threadIdx.x == 0) nz = 0;
        __syncthreads();
        int pairs = E < 2048 ? E : 2048;
        int cnt = 0;
        for (int j = threadIdx.x; j < pairs; j += blockDim.x)
            if (ei32[2 * j + 1] != 0) cnt++;
        if (cnt) atomicOr(&nz, 1);
        __syncthreads();
        if (threadIdx.x == 0) g_is64 = (nz == 0) ? 1 : 0;
    }
}

__device__ __forceinline__ int load_idx(const void* ei, long long i) {
    return g_is64 ? (int)((const long long*)ei)[i] : ((const int*)ei)[i];
}

__global__ void hist_kernel(const void* __restrict__ ei, int E) {
    int i = blockIdx.x * blockDim.x + threadIdx.x;
    if (i >= E) return;
    atomicAdd(&g_deg[load_idx(ei, (long long)E + i)], 1);
}

// Single-pass exclusive scan of g_deg via decoupled lookback.
// grid = nb (<=49) blocks, all resident -> lookback cannot deadlock.
__global__ void __launch_bounds__(256) csr_scan(int N, int nb) {
    __shared__ int sh[256];
    __shared__ int sbase;
    int b = blockIdx.x, tid = threadIdx.x;
    int i0 = b * 1024 + tid * 4;
    int d0 = 0, d1 = 0, d2 = 0, d3 = 0;
    if (i0 + 0 < N) d0 = g_deg[i0 + 0];
    if (i0 + 1 < N) d1 = g_deg[i0 + 1];
    if (i0 + 2 < N) d2 = g_deg[i0 + 2];
    if (i0 + 3 < N) d3 = g_deg[i0 + 3];
    int tsum = d0 + d1 + d2 + d3;
    sh[tid] = tsum;
    __syncthreads();
    for (int d = 1; d < 256; d <<= 1) {
        int t = (tid >= d) ? sh[tid - d] : 0;
        __syncthreads();
        sh[tid] += t;
        __syncthreads();
    }
    int agg = sh[255];   // block total
    if (tid == 0) {
        if (b == 0) {
            atomicExch(&g_look[0], (2ull << 32) | (unsigned)agg);
            sbase = 0;
        } else {
            atomicExch(&g_look[b], (1ull << 32) | (unsigned)agg);
            int ex = 0;
            int i = b - 1;
            while (true) {
                unsigned long long v;
                do { v = atomicAdd(&g_look[i], 0ull); } while ((v >> 32) == 0ull);
                ex += (int)(unsigned)v;
                if ((v >> 32) == 2ull) break;
                --i;
            }
            atomicExch(&g_look[b], (2ull << 32) | (unsigned)(ex + agg));
            sbase = ex;
        }
    }
    __syncthreads();
    int o0 = sbase + sh[tid] - tsum;
    int o1 = o0 + d0, o2 = o1 + d1, o3 = o2 + d2;
    if (i0 + 0 < N) { g_off[i0 + 0] = o0; g_pos[i0 + 0] = o0; }
    if (i0 + 1 < N) { g_off[i0 + 1] = o1; g_pos[i0 + 1] = o1; }
    if (i0 + 2 < N) { g_off[i0 + 2] = o2; g_pos[i0 + 2] = o2; }
    if (i0 + 3 < N) { g_off[i0 + 3] = o3; g_pos[i0 + 3] = o3; }
    if (b == nb - 1 && tid == 255) g_off[N] = sbase + agg;
}

__global__ void permute_kernel(const void* __restrict__ ei, int E) {
    int i = blockIdx.x * blockDim.x + threadIdx.x;
    if (i >= E) return;
    int src = load_idx(ei, i);
    int dst = load_idx(ei, (long long)E + i);
    g_srcsorted[atomicAdd(&g_pos[dst], 1)] = src;
}

// ---------------------------------------------------------------------------
// 3xTF32 tensor-core GEMM, 128x128 CTA tile, 8 warps = 4x2 warp grid.
// BN1=false (gemm1): A-tile produced IN-KERNEL by CSR gather of x
//                    (agg = (1+eps)*x[node] + sum x[nbr]); C=g_h1,
//                    stats -> g_stats[0/128].
// BN1=true  (gemm2): A = relu(BN1(g_h1)) folded on load; C=outp,
//                    stats -> g_stats[256/384].
// ---------------------------------------------------------------------------
#define SMO_A     0                     // float A[128][132]
#define SMO_BH    67584                 // uint32 Bhi[128][132]
#define SMO_BL    135168                // uint32 Blo[128][132]
#define SMO_BIAS  202752                // float[128]
#define SMO_SA    203264                // float[128]
#define SMO_SC    203776                // float[128]
#define SMO_SS    204288                // float[128]
#define SMO_SQ    204800                // float[128]
#define SMEM_GEMM 205312

__device__ __forceinline__ uint32_t f2tf32(float x) {
    uint32_t r;
    asm("cvt.rna.tf32.f32 %0, %1;" : "=r"(r) : "f"(x));
    return r;
}

__device__ __forceinline__ void mma_tf32(float* d, const uint32_t* a,
                                         uint32_t b0, uint32_t b1) {
    asm volatile(
        "mma.sync.aligned.m16n8k8.row.col.f32.tf32.tf32.f32 "
        "{%0,%1,%2,%3}, {%4,%5,%6,%7}, {%8,%9}, {%0,%1,%2,%3};"
        : "+f"(d[0]), "+f"(d[1]), "+f"(d[2]), "+f"(d[3])
        : "r"(a[0]), "r"(a[1]), "r"(a[2]), "r"(a[3]), "r"(b0), "r"(b1));
}

template <bool BN1>
__global__ void __launch_bounds__(256, 1)
gemm_mma(const float* __restrict__ W, const float* __restrict__ bias,
         const float* __restrict__ x, const float* __restrict__ eps,
         const float* __restrict__ gamma, const float* __restrict__ beta,
         float* __restrict__ outp, int N, float invN) {
    float* C       = BN1 ? outp : g_h1;
    float* statSum = BN1 ? (g_stats + 256) : g_stats;
    float* statSq  = BN1 ? (g_stats + 384) : (g_stats + 128);

    extern __shared__ __align__(16) char smem[];
    float*    As = (float*)(smem + SMO_A);
    uint32_t* Bh = (uint32_t*)(smem + SMO_BH);
    uint32_t* Bl = (uint32_t*)(smem + SMO_BL);
    float* sbias = (float*)(smem + SMO_BIAS);
    float* s_a   = (float*)(smem + SMO_SA);
    float* s_c   = (float*)(smem + SMO_SC);
    float* sS    = (float*)(smem + SMO_SS);
    float* sQ    = (float*)(smem + SMO_SQ);

    int tid = threadIdx.x, wid = tid >> 5, lane = tid & 31;
    int wr = wid >> 1;        // 0..3 : rows wr*32 .. +32
    int wc = wid & 1;         // 0..1 : cols wc*64 .. +64
    int gid = lane >> 2;      // 0..7
    int tig = lane & 3;       // 0..3
    int m0 = blockIdx.x * 128;

    if (tid < 128) {
        sbias[tid] = bias[tid];
        sS[tid] = 0.f;
        sQ[tid] = 0.f;
        if (BN1) {
            float mu  = g_stats[tid] * invN;
            float var = g_stats[128 + tid] * invN - mu * mu;
            float a = gamma[tid] * rsqrtf(var + 1e-5f);
            s_a[tid] = a;
            s_c[tid] = beta[tid] - mu * a;
        }
    }
    __syncthreads();

    if (BN1) {
        // ---- A = relu(BN1(g_h1)) ----
#pragma unroll
        for (int it = 0; it < 16; ++it) {
            int idx = tid + it * 256;
            int row = idx >> 5;
            int k0  = (idx & 31) << 2;
            int gm = m0 + row; if (gm >= N) gm = N - 1;
            float4 v = *(const float4*)(g_h1 + (size_t)gm * 128 + k0);
            v.x = fmaxf(fmaf(v.x, s_a[k0 + 0], s_c[k0 + 0]), 0.f);
            v.y = fmaxf(fmaf(v.y, s_a[k0 + 1], s_c[k0 + 1]), 0.f);
            v.z = fmaxf(fmaf(v.z, s_a[k0 + 2], s_c[k0 + 2]), 0.f);
            v.w = fmaxf(fmaf(v.w, s_a[k0 + 3], s_c[k0 + 3]), 0.f);
            *(float4*)(As + row * 132 + k0) = v;
        }
    } else {
        // ---- A = GIN aggregation, gathered via CSR (warp w: rows w*16..+15)
        const float4* x4 = (const float4*)x;
        float s = 1.f + eps[0];
#pragma unroll 1
        for (int rr = 0; rr < 16; ++rr) {
            int row = wid * 16 + rr;
            int gm = m0 + row; if (gm >= N) gm = N - 1;
            float4 acc = x4[(size_t)gm * 32 + lane];
            acc.x *= s; acc.y *= s; acc.z *= s; acc.w *= s;
            float4 acc2 = make_float4(0.f, 0.f, 0.f, 0.f);
            int j = g_off[gm], end = g_off[gm + 1];
            for (; j + 3 < end; j += 4) {
                int s0 = g_srcsorted[j + 0];
                int s1 = g_srcsorted[j + 1];
                int s2 = g_srcsorted[j + 2];
                int s3 = g_srcsorted[j + 3];
                float4 v0 = x4[(size_t)s0 * 32 + lane];
                float4 v1 = x4[(size_t)s1 * 32 + lane];
                float4 v2 = x4[(size_t)s2 * 32 + lane];
                float4 v3 = x4[(size_t)s3 * 32 + lane];
                acc.x  += v0.x + v1.x; acc.y  += v0.y + v1.y;
                acc.z  += v0.z + v1.z; acc.w  += v0.w + v1.w;
                acc2.x += v2.x + v3.x; acc2.y += v2.y + v3.y;
                acc2.z += v2.z + v3.z; acc2.w += v2.w + v3.w;
            }
            for (; j < end; j++) {
                float4 v0 = x4[(size_t)g_srcsorted[j] * 32 + lane];
                acc.x += v0.x; acc.y += v0.y; acc.z += v0.z; acc.w += v0.w;
            }
            acc.x += acc2.x; acc.y += acc2.y;
            acc.z += acc2.z; acc.w += acc2.w;
            *(float4*)(As + row * 132 + lane * 4) = acc;
        }
    }
    // ---- load W, split into Bhi/Blo tf32 ----
#pragma unroll
    for (int it = 0; it < 16; ++it) {
        int idx = tid + it * 256;
        int row = idx >> 5;              // n
        int k0  = (idx & 31) << 2;
        float4 v = *(const float4*)(W + (size_t)row * 128 + k0);
        float f[4] = {v.x, v.y, v.z, v.w};
        uint32_t hi[4], lo[4];
#pragma unroll
        for (int j = 0; j < 4; ++j) {
            hi[j] = f2tf32(f[j]);
            lo[j] = f2tf32(f[j] - __uint_as_float(hi[j]));
        }
        *(uint4*)(Bh + row * 132 + k0) = make_uint4(hi[0], hi[1], hi[2], hi[3]);
        *(uint4*)(Bl + row * 132 + k0) = make_uint4(lo[0], lo[1], lo[2], lo[3]);
    }
    __syncthreads();

    // ---- mainloop ----
    float acc[2][8][4];
#pragma unroll
    for (int mt = 0; mt < 2; ++mt)
#pragma unroll
        for (int nt = 0; nt < 8; ++nt)
#pragma unroll
            for (int r = 0; r < 4; ++r) acc[mt][nt][r] = 0.f;

#pragma unroll 4
    for (int ks = 0; ks < 16; ++ks) {
        int k0 = ks * 8;
        uint32_t ahi[2][4], alo[2][4];
#pragma unroll
        for (int mt = 0; mt < 2; ++mt) {
            int r0 = wr * 32 + mt * 16 + gid;
            float a0 = As[r0 * 132 + k0 + tig];
            float a1 = As[(r0 + 8) * 132 + k0 + tig];
            float a2 = As[r0 * 132 + k0 + tig + 4];
            float a3 = As[(r0 + 8) * 132 + k0 + tig + 4];
            ahi[mt][0] = f2tf32(a0); alo[mt][0] = f2tf32(a0 - __uint_as_float(ahi[mt][0]));
            ahi[mt][1] = f2tf32(a1); alo[mt][1] = f2tf32(a1 - __uint_as_float(ahi[mt][1]));
            ahi[mt][2] = f2tf32(a2); alo[mt][2] = f2tf32(a2 - __uint_as_float(ahi[mt][2]));
            ahi[mt][3] = f2tf32(a3); alo[mt][3] = f2tf32(a3 - __uint_as_float(ahi[mt][3]));
        }
#pragma unroll
        for (int nt = 0; nt < 8; ++nt) {
            int n = wc * 64 + nt * 8 + gid;
            uint32_t bh0 = Bh[n * 132 + k0 + tig];
            uint32_t bh1 = Bh[n * 132 + k0 + tig + 4];
            uint32_t bl0 = Bl[n * 132 + k0 + tig];
            uint32_t bl1 = Bl[n * 132 + k0 + tig + 4];
#pragma unroll
            for (int mt = 0; mt < 2; ++mt) {
                mma_tf32(acc[mt][nt], ahi[mt], bh0, bh1);
                mma_tf32(acc[mt][nt], ahi[mt], bl0, bl1);
                mma_tf32(acc[mt][nt], alo[mt], bh0, bh1);
            }
        }
    }

    // ---- epilogue: bias add, store, fused column stats ----
    float ls[16], lq[16];
#pragma unroll
    for (int i = 0; i < 16; ++i) { ls[i] = 0.f; lq[i] = 0.f; }

#pragma unroll
    for (int mt = 0; mt < 2; ++mt) {
        int grow0 = m0 + wr * 32 + mt * 16 + gid;
        int grow1 = grow0 + 8;
        bool v0 = grow0 < N, v1 = grow1 < N;
#pragma unroll
        for (int nt = 0; nt < 8; ++nt) {
            int gcol = wc * 64 + nt * 8 + tig * 2;
            float d0 = acc[mt][nt][0] + sbias[gcol];
            float d1 = acc[mt][nt][1] + sbias[gcol + 1];
            float d2 = acc[mt][nt][2] + sbias[gcol];
            float d3 = acc[mt][nt][3] + sbias[gcol + 1];
            if (v0) {
                *(float2*)(C + (size_t)grow0 * 128 + gcol) = make_float2(d0, d1);
                ls[nt * 2]     += d0; lq[nt * 2]     = fmaf(d0, d0, lq[nt * 2]);
                ls[nt * 2 + 1] += d1; lq[nt * 2 + 1] = fmaf(d1, d1, lq[nt * 2 + 1]);
            }
            if (v1) {
                *(float2*)(C + (size_t)grow1 * 128 + gcol) = make_float2(d2, d3);
                ls[nt * 2]     += d2; lq[nt * 2]     = fmaf(d2, d2, lq[nt * 2]);
                ls[nt * 2 + 1] += d3; lq[nt * 2 + 1] = fmaf(d3, d3, lq[nt * 2 + 1]);
            }
        }
    }
#pragma unroll
    for (int d = 4; d < 32; d <<= 1) {
#pragma unroll
        for (int i = 0; i < 16; ++i) {
            ls[i] += __shfl_xor_sync(0xFFFFFFFFu, ls[i], d);
            lq[i] += __shfl_xor_sync(0xFFFFFFFFu, lq[i], d);
        }
    }
    if (gid == 0) {
#pragma unroll
        for (int i = 0; i < 16; ++i) {
            int col = wc * 64 + (i >> 1) * 8 + tig * 2 + (i & 1);
            atomicAdd(&sS[col], ls[i]);
            atomicAdd(&sQ[col], lq[i]);
        }
    }
    __syncthreads();
    if (tid < 128) {
        atomicAdd(&statSum[tid], sS[tid]);
        atomicAdd(&statSq[tid],  sQ[tid]);
    }
}

// out = relu(BN2(out)), BN2 affine computed per block from g_stats.
__global__ void __launch_bounds__(256)
bnrelu_kernel(float* __restrict__ out,
              const float* __restrict__ gamma, const float* __restrict__ beta,
              int N, float invN) {
    __shared__ float s_a[128], s_c[128];
    int tid = threadIdx.x;
    if (tid < 128) {
        float mu  = g_stats[256 + tid] * invN;
        float var = g_stats[384 + tid] * invN - mu * mu;
        float a = gamma[tid] * rsqrtf(var + 1e-5f);
        s_a[tid] = a;
        s_c[tid] = beta[tid] - mu * a;
    }
    __syncthreads();
    int c4 = (tid & 31) << 2;
    float4 a4  = *(const float4*)(s_a + c4);
    float4 c4v = *(const float4*)(s_c + c4);
    int rows_per_iter = gridDim.x * (blockDim.x >> 5);
    int r = blockIdx.x * (blockDim.x >> 5) + (tid >> 5);
    float4* o4 = (float4*)out;
    for (; r < N; r += rows_per_iter) {
        size_t idx = (size_t)r * 32 + (tid & 31);
        float4 v = o4[idx];
        v.x = fmaxf(fmaf(v.x, a4.x, c4v.x), 0.f);
        v.y = fmaxf(fmaf(v.y, a4.y, c4v.y), 0.f);
        v.z = fmaxf(fmaf(v.z, a4.z, c4v.z), 0.f);
        v.w = fmaxf(fmaf(v.w, a4.w, c4v.w), 0.f);
        o4[idx] = v;
    }
}

// ---------------------------------------------------------------------------
extern "C" void kernel_launch(void* const* d_in, const int* in_sizes, int n_in,
                              void* d_out, int out_size) {
    const float* x   = (const float*)d_in[0];
    const void*  ei  = d_in[1];
    const float* eps = (const float*)d_in[2];
    const float* W1  = (const float*)d_in[3];
    const float* b1  = (const float*)d_in[4];
    const float* g1  = (const float*)d_in[5];
    const float* be1 = (const float*)d_in[6];
    const float* W2  = (const float*)d_in[7];
    const float* b2  = (const float*)d_in[8];
    const float* g2  = (const float*)d_in[9];
    const float* be2 = (const float*)d_in[10];

    int N = in_sizes[0] / 128;
    int E = in_sizes[1] / 2;
    if (E > MAXE) E = MAXE;
    float* out = (float*)d_out;
    float invN = 1.f / (float)N;
    int nb = (N + 1023) / 1024;

    cudaFuncSetAttribute(gemm_mma<false>,
                         cudaFuncAttributeMaxDynamicSharedMemorySize, SMEM_GEMM);
    cudaFuncSetAttribute(gemm_mma<true>,
                         cudaFuncAttributeMaxDynamicSharedMemorySize, SMEM_GEMM);

    init_kernel<<<(N + 256) / 256, 256>>>((const int*)ei, E, N);
    hist_kernel<<<(E + 255) / 256, 256>>>(ei, E);
    csr_scan<<<nb, 256>>>(N, nb);
    permute_kernel<<<(E + 255) / 256, 256>>>(ei, E);

    int gblocks = (N + 127) / 128;
    gemm_mma<false><<<gblocks, 256, SMEM_GEMM>>>(W1, b1, x, eps,
                                                 nullptr, nullptr,
                                                 nullptr, N, invN);
    gemm_mma<true><<<gblocks, 256, SMEM_GEMM>>>(W2, b2, nullptr, nullptr,
                                                g1, be1, out, N, invN);
    bnrelu_kernel<<<592, 256>>>(out, g2, be2, N, invN);
}

// round 9
// speedup vs baseline: 1.4345x; 1.4345x over previous
#include <cuda_runtime.h>
#include <cstdint>

// ---------------------------------------------------------------------------
// GIN block. 8-kernel pipeline:
//   init (dtype detect + zero) -> hist -> single-pass lookback scan ->
//   permute -> aggregate (CSR gather, full occupancy) ->
//   gemm1 (mma.sync 3xTF32, fused BN1 stats) ->
//   gemm2 (BN1+ReLU folded on load, fused BN2 stats) -> bnrelu.
// R8 lesson: do NOT fuse the gather into the 1-CTA/SM GEMM (8 warps can't
// hide L2 gather latency). R6 lesson: __device__ symbols only from device code.
// ---------------------------------------------------------------------------

#define MAXN 50048
#define MAXE 1600000

__device__ __align__(16) float g_agg[MAXN * 128];
__device__ __align__(16) float g_h1[MAXN * 128];
__device__ float g_stats[512];   // [sum1, sumsq1, sum2, sumsq2] x 128
__device__ int   g_deg[MAXN + 1];
__device__ int   g_off[MAXN + 1];
__device__ int   g_pos[MAXN + 1];
__device__ unsigned long long g_look[64];  // lookback: flag(hi32) | value(lo32)
__device__ int   g_srcsorted[MAXE];
__device__ int   g_is64;

// ---------------------------------------------------------------------------
// init: zero histogram/stats/lookback; block 0 also detects edge dtype.
// int64 node ids < 2^31 -> every odd int32 word is zero; int32 edges -> not.
__global__ void init_kernel(const int* __restrict__ ei32, int E, int N) {
    int i = blockIdx.x * blockDim.x + threadIdx.x;
    if (i <= N) g_deg[i] = 0;
    if (i < 512) g_stats[i] = 0.f;
    if (i < 64) g_look[i] = 0ull;
    if (blockIdx.x == 0) {
        __shared__ int nz;
        if (threadIdx.x == 0) nz = 0;
        __syncthreads();
        int pairs = E < 2048 ? E : 2048;
        int cnt = 0;
        for (int j = threadIdx.x; j < pairs; j += blockDim.x)
            if (ei32[2 * j + 1] != 0) cnt++;
        if (cnt) atomicOr(&nz, 1);
        __syncthreads();
        if (threadIdx.x == 0) g_is64 = (nz == 0) ? 1 : 0;
    }
}

__device__ __forceinline__ int load_idx(const void* ei, long long i) {
    return g_is64 ? (int)((const long long*)ei)[i] : ((const int*)ei)[i];
}

__global__ void hist_kernel(const void* __restrict__ ei, int E) {
    int i = blockIdx.x * blockDim.x + threadIdx.x;
    if (i >= E) return;
    atomicAdd(&g_deg[load_idx(ei, (long long)E + i)], 1);
}

// Single-pass exclusive scan of g_deg via decoupled lookback.
// grid = nb (<=49) blocks, all resident -> lookback cannot deadlock.
__global__ void __launch_bounds__(256) csr_scan(int N, int nb) {
    __shared__ int sh[256];
    __shared__ int sbase;
    int b = blockIdx.x, tid = threadIdx.x;
    int i0 = b * 1024 + tid * 4;
    int d0 = 0, d1 = 0, d2 = 0, d3 = 0;
    if (i0 + 0 < N) d0 = g_deg[i0 + 0];
    if (i0 + 1 < N) d1 = g_deg[i0 + 1];
    if (i0 + 2 < N) d2 = g_deg[i0 + 2];
    if (i0 + 3 < N) d3 = g_deg[i0 + 3];
    int tsum = d0 + d1 + d2 + d3;
    sh[tid] = tsum;
    __syncthreads();
    for (int d = 1; d < 256; d <<= 1) {
        int t = (tid >= d) ? sh[tid - d] : 0;
        __syncthreads();
        sh[tid] += t;
        __syncthreads();
    }
    int agg = sh[255];   // block total
    if (tid == 0) {
        if (b == 0) {
            atomicExch(&g_look[0], (2ull << 32) | (unsigned)agg);
            sbase = 0;
        } else {
            atomicExch(&g_look[b], (1ull << 32) | (unsigned)agg);
            int ex = 0;
            int i = b - 1;
            while (true) {
                unsigned long long v;
                do { v = atomicAdd(&g_look[i], 0ull); } while ((v >> 32) == 0ull);
                ex += (int)(unsigned)v;
                if ((v >> 32) == 2ull) break;
                --i;
            }
            atomicExch(&g_look[b], (2ull << 32) | (unsigned)(ex + agg));
            sbase = ex;
        }
    }
    __syncthreads();
    int o0 = sbase + sh[tid] - tsum;
    int o1 = o0 + d0, o2 = o1 + d1, o3 = o2 + d2;
    if (i0 + 0 < N) { g_off[i0 + 0] = o0; g_pos[i0 + 0] = o0; }
    if (i0 + 1 < N) { g_off[i0 + 1] = o1; g_pos[i0 + 1] = o1; }
    if (i0 + 2 < N) { g_off[i0 + 2] = o2; g_pos[i0 + 2] = o2; }
    if (i0 + 3 < N) { g_off[i0 + 3] = o3; g_pos[i0 + 3] = o3; }
    if (b == nb - 1 && tid == 255) g_off[N] = sbase + agg;
}

__global__ void permute_kernel(const void* __restrict__ ei, int E) {
    int i = blockIdx.x * blockDim.x + threadIdx.x;
    if (i >= E) return;
    int src = load_idx(ei, i);
    int dst = load_idx(ei, (long long)E + i);
    g_srcsorted[atomicAdd(&g_pos[dst], 1)] = src;
}

// One warp per node: acc = (1+eps)*x[node] + sum of neighbor rows; one store.
// Full occupancy -> enough MLP to hide the L2 gather latency (R8 lesson).
__global__ void aggregate_kernel(const float* __restrict__ x,
                                 const float* __restrict__ eps, int N) {
    int w = (int)((blockIdx.x * blockDim.x + threadIdx.x) >> 5);
    if (w >= N) return;
    int lane = threadIdx.x & 31;
    const float4* x4 = (const float4*)x;
    float s = 1.f + eps[0];
    float4 acc = x4[(size_t)w * 32 + lane];
    acc.x *= s; acc.y *= s; acc.z *= s; acc.w *= s;
    float4 acc2 = make_float4(0.f, 0.f, 0.f, 0.f);
    int j = g_off[w], end = g_off[w + 1];
    for (; j + 3 < end; j += 4) {
        int s0 = g_srcsorted[j + 0];
        int s1 = g_srcsorted[j + 1];
        int s2 = g_srcsorted[j + 2];
        int s3 = g_srcsorted[j + 3];
        float4 v0 = x4[(size_t)s0 * 32 + lane];
        float4 v1 = x4[(size_t)s1 * 32 + lane];
        float4 v2 = x4[(size_t)s2 * 32 + lane];
        float4 v3 = x4[(size_t)s3 * 32 + lane];
        acc.x  += v0.x + v1.x; acc.y  += v0.y + v1.y;
        acc.z  += v0.z + v1.z; acc.w  += v0.w + v1.w;
        acc2.x += v2.x + v3.x; acc2.y += v2.y + v3.y;
        acc2.z += v2.z + v3.z; acc2.w += v2.w + v3.w;
    }
    for (; j < end; j++) {
        float4 v0 = x4[(size_t)g_srcsorted[j] * 32 + lane];
        acc.x += v0.x; acc.y += v0.y; acc.z += v0.z; acc.w += v0.w;
    }
    acc.x += acc2.x; acc.y += acc2.y; acc.z += acc2.z; acc.w += acc2.w;
    ((float4*)g_agg)[(size_t)w * 32 + lane] = acc;
}

// ---------------------------------------------------------------------------
// 3xTF32 tensor-core GEMM, 128x128 CTA tile, 8 warps = 4x2 warp grid.
// BN1=false (gemm1): A=g_agg, C=g_h1, stats -> g_stats[0/128].
// BN1=true  (gemm2): A=relu(BN1(g_h1)) folded on load, C=outp,
//                    stats -> g_stats[256/384].
// ---------------------------------------------------------------------------
#define SMO_A     0                     // float A[128][132]
#define SMO_BH    67584                 // uint32 Bhi[128][132]
#define SMO_BL    135168                // uint32 Blo[128][132]
#define SMO_BIAS  202752                // float[128]
#define SMO_SA    203264                // float[128]
#define SMO_SC    203776                // float[128]
#define SMO_SS    204288                // float[128]
#define SMO_SQ    204800                // float[128]
#define SMEM_GEMM 205312

__device__ __forceinline__ uint32_t f2tf32(float x) {
    uint32_t r;
    asm("cvt.rna.tf32.f32 %0, %1;" : "=r"(r) : "f"(x));
    return r;
}

__device__ __forceinline__ void mma_tf32(float* d, const uint32_t* a,
                                         uint32_t b0, uint32_t b1) {
    asm volatile(
        "mma.sync.aligned.m16n8k8.row.col.f32.tf32.tf32.f32 "
        "{%0,%1,%2,%3}, {%4,%5,%6,%7}, {%8,%9}, {%0,%1,%2,%3};"
        : "+f"(d[0]), "+f"(d[1]), "+f"(d[2]), "+f"(d[3])
        : "r"(a[0]), "r"(a[1]), "r"(a[2]), "r"(a[3]), "r"(b0), "r"(b1));
}

template <bool BN1>
__global__ void __launch_bounds__(256, 1)
gemm_mma(const float* __restrict__ W, const float* __restrict__ bias,
         const float* __restrict__ gamma, const float* __restrict__ beta,
         float* __restrict__ outp, int N, float invN) {
    // Bind device symbols in device code (R6 lesson).
    const float* A  = BN1 ? g_h1 : g_agg;
    float* C        = BN1 ? outp : g_h1;
    float* statSum  = BN1 ? (g_stats + 256) : g_stats;
    float* statSq   = BN1 ? (g_stats + 384) : (g_stats + 128);

    extern __shared__ __align__(16) char smem[];
    float*    As = (float*)(smem + SMO_A);
    uint32_t* Bh = (uint32_t*)(smem + SMO_BH);
    uint32_t* Bl = (uint32_t*)(smem + SMO_BL);
    float* sbias = (float*)(smem + SMO_BIAS);
    float* s_a   = (float*)(smem + SMO_SA);
    float* s_c   = (float*)(smem + SMO_SC);
    float* sS    = (float*)(smem + SMO_SS);
    float* sQ    = (float*)(smem + SMO_SQ);

    int tid = threadIdx.x, wid = tid >> 5, lane = tid & 31;
    int wr = wid >> 1;        // 0..3 : rows wr*32 .. +32
    int wc = wid & 1;         // 0..1 : cols wc*64 .. +64
    int gid = lane >> 2;      // 0..7
    int tig = lane & 3;       // 0..3
    int m0 = blockIdx.x * 128;

    if (tid < 128) {
        sbias[tid] = bias[tid];
        sS[tid] = 0.f;
        sQ[tid] = 0.f;
        if (BN1) {
            float mu  = g_stats[tid] * invN;
            float var = g_stats[128 + tid] * invN - mu * mu;
            float a = gamma[tid] * rsqrtf(var + 1e-5f);
            s_a[tid] = a;
            s_c[tid] = beta[tid] - mu * a;
        }
    }
    __syncthreads();   // s_a/s_c ready before A load

    // ---- load A tile (fp32, BN1+ReLU folded for gemm2) ----
#pragma unroll
    for (int it = 0; it < 16; ++it) {
        int idx = tid + it * 256;        // 0..4095
        int row = idx >> 5;              // 0..127
        int k0  = (idx & 31) << 2;       // 0..124
        int gm = m0 + row; if (gm >= N) gm = N - 1;
        float4 v = *(const float4*)(A + (size_t)gm * 128 + k0);
        if (BN1) {
            v.x = fmaxf(fmaf(v.x, s_a[k0 + 0], s_c[k0 + 0]), 0.f);
            v.y = fmaxf(fmaf(v.y, s_a[k0 + 1], s_c[k0 + 1]), 0.f);
            v.z = fmaxf(fmaf(v.z, s_a[k0 + 2], s_c[k0 + 2]), 0.f);
            v.w = fmaxf(fmaf(v.w, s_a[k0 + 3], s_c[k0 + 3]), 0.f);
        }
        *(float4*)(As + row * 132 + k0) = v;
    }
    // ---- load W, split into Bhi/Blo tf32 ----
#pragma unroll
    for (int it = 0; it < 16; ++it) {
        int idx = tid + it * 256;
        int row = idx >> 5;              // n
        int k0  = (idx & 31) << 2;
        float4 v = *(const float4*)(W + (size_t)row * 128 + k0);
        float f[4] = {v.x, v.y, v.z, v.w};
        uint32_t hi[4], lo[4];
#pragma unroll
        for (int j = 0; j < 4; ++j) {
            hi[j] = f2tf32(f[j]);
            lo[j] = f2tf32(f[j] - __uint_as_float(hi[j]));
        }
        *(uint4*)(Bh + row * 132 + k0) = make_uint4(hi[0], hi[1], hi[2], hi[3]);
        *(uint4*)(Bl + row * 132 + k0) = make_uint4(lo[0], lo[1], lo[2], lo[3]);
    }
    __syncthreads();

    // ---- mainloop ----
    float acc[2][8][4];
#pragma unroll
    for (int mt = 0; mt < 2; ++mt)
#pragma unroll
        for (int nt = 0; nt < 8; ++nt)
#pragma unroll
            for (int r = 0; r < 4; ++r) acc[mt][nt][r] = 0.f;

#pragma unroll 4
    for (int ks = 0; ks < 16; ++ks) {
        int k0 = ks * 8;
        uint32_t ahi[2][4], alo[2][4];
#pragma unroll
        for (int mt = 0; mt < 2; ++mt) {
            int r0 = wr * 32 + mt * 16 + gid;
            float a0 = As[r0 * 132 + k0 + tig];
            float a1 = As[(r0 + 8) * 132 + k0 + tig];
            float a2 = As[r0 * 132 + k0 + tig + 4];
            float a3 = As[(r0 + 8) * 132 + k0 + tig + 4];
            ahi[mt][0] = f2tf32(a0); alo[mt][0] = f2tf32(a0 - __uint_as_float(ahi[mt][0]));
            ahi[mt][1] = f2tf32(a1); alo[mt][1] = f2tf32(a1 - __uint_as_float(ahi[mt][1]));
            ahi[mt][2] = f2tf32(a2); alo[mt][2] = f2tf32(a2 - __uint_as_float(ahi[mt][2]));
            ahi[mt][3] = f2tf32(a3); alo[mt][3] = f2tf32(a3 - __uint_as_float(ahi[mt][3]));
        }
#pragma unroll
        for (int nt = 0; nt < 8; ++nt) {
            int n = wc * 64 + nt * 8 + gid;
            uint32_t bh0 = Bh[n * 132 + k0 + tig];
            uint32_t bh1 = Bh[n * 132 + k0 + tig + 4];
            uint32_t bl0 = Bl[n * 132 + k0 + tig];
            uint32_t bl1 = Bl[n * 132 + k0 + tig + 4];
#pragma unroll
            for (int mt = 0; mt < 2; ++mt) {
                mma_tf32(acc[mt][nt], ahi[mt], bh0, bh1);
                mma_tf32(acc[mt][nt], ahi[mt], bl0, bl1);
                mma_tf32(acc[mt][nt], alo[mt], bh0, bh1);
            }
        }
    }

    // ---- epilogue: bias add, store, fused column stats ----
    float ls[16], lq[16];
#pragma unroll
    for (int i = 0; i < 16; ++i) { ls[i] = 0.f; lq[i] = 0.f; }

#pragma unroll
    for (int mt = 0; mt < 2; ++mt) {
        int grow0 = m0 + wr * 32 + mt * 16 + gid;
        int grow1 = grow0 + 8;
        bool v0 = grow0 < N, v1 = grow1 < N;
#pragma unroll
        for (int nt = 0; nt < 8; ++nt) {
            int gcol = wc * 64 + nt * 8 + tig * 2;
            float d0 = acc[mt][nt][0] + sbias[gcol];
            float d1 = acc[mt][nt][1] + sbias[gcol + 1];
            float d2 = acc[mt][nt][2] + sbias[gcol];
            float d3 = acc[mt][nt][3] + sbias[gcol + 1];
            if (v0) {
                *(float2*)(C + (size_t)grow0 * 128 + gcol) = make_float2(d0, d1);
                ls[nt * 2]     += d0; lq[nt * 2]     = fmaf(d0, d0, lq[nt * 2]);
                ls[nt * 2 + 1] += d1; lq[nt * 2 + 1] = fmaf(d1, d1, lq[nt * 2 + 1]);
            }
            if (v1) {
                *(float2*)(C + (size_t)grow1 * 128 + gcol) = make_float2(d2, d3);
                ls[nt * 2]     += d2; lq[nt * 2]     = fmaf(d2, d2, lq[nt * 2]);
                ls[nt * 2 + 1] += d3; lq[nt * 2 + 1] = fmaf(d3, d3, lq[nt * 2 + 1]);
            }
        }
    }
    // reduce across the 8 row-owning lanes (gid) of the warp
#pragma unroll
    for (int d = 4; d < 32; d <<= 1) {
#pragma unroll
        for (int i = 0; i < 16; ++i) {
            ls[i] += __shfl_xor_sync(0xFFFFFFFFu, ls[i], d);
            lq[i] += __shfl_xor_sync(0xFFFFFFFFu, lq[i], d);
        }
    }
    if (gid == 0) {
#pragma unroll
        for (int i = 0; i < 16; ++i) {
            int col = wc * 64 + (i >> 1) * 8 + tig * 2 + (i & 1);
            atomicAdd(&sS[col], ls[i]);
            atomicAdd(&sQ[col], lq[i]);
        }
    }
    __syncthreads();
    if (tid < 128) {
        atomicAdd(&statSum[tid], sS[tid]);
        atomicAdd(&statSq[tid],  sQ[tid]);
    }
}

// out = relu(BN2(out)), BN2 affine computed per block from g_stats.
__global__ void __launch_bounds__(256)
bnrelu_kernel(float* __restrict__ out,
              const float* __restrict__ gamma, const float* __restrict__ beta,
              int N, float invN) {
    __shared__ float s_a[128], s_c[128];
    int tid = threadIdx.x;
    if (tid < 128) {
        float mu  = g_stats[256 + tid] * invN;
        float var = g_stats[384 + tid] * invN - mu * mu;
        float a = gamma[tid] * rsqrtf(var + 1e-5f);
        s_a[tid] = a;
        s_c[tid] = beta[tid] - mu * a;
    }
    __syncthreads();
    int c4 = (tid & 31) << 2;
    float4 a4  = *(const float4*)(s_a + c4);
    float4 c4v = *(const float4*)(s_c + c4);
    int rows_per_iter = gridDim.x * (blockDim.x >> 5);
    int r = blockIdx.x * (blockDim.x >> 5) + (tid >> 5);
    float4* o4 = (float4*)out;
    for (; r < N; r += rows_per_iter) {
        size_t idx = (size_t)r * 32 + (tid & 31);
        float4 v = o4[idx];
        v.x = fmaxf(fmaf(v.x, a4.x, c4v.x), 0.f);
        v.y = fmaxf(fmaf(v.y, a4.y, c4v.y), 0.f);
        v.z = fmaxf(fmaf(v.z, a4.z, c4v.z), 0.f);
        v.w = fmaxf(fmaf(v.w, a4.w, c4v.w), 0.f);
        o4[idx] = v;
    }
}

// ---------------------------------------------------------------------------
extern "C" void kernel_launch(void* const* d_in, const int* in_sizes, int n_in,
                              void* d_out, int out_size) {
    const float* x   = (const float*)d_in[0];
    const void*  ei  = d_in[1];
    const float* eps = (const float*)d_in[2];
    const float* W1  = (const float*)d_in[3];
    const float* b1  = (const float*)d_in[4];
    const float* g1  = (const float*)d_in[5];
    const float* be1 = (const float*)d_in[6];
    const float* W2  = (const float*)d_in[7];
    const float* b2  = (const float*)d_in[8];
    const float* g2  = (const float*)d_in[9];
    const float* be2 = (const float*)d_in[10];

    int N = in_sizes[0] / 128;
    int E = in_sizes[1] / 2;
    if (E > MAXE) E = MAXE;
    float* out = (float*)d_out;
    float invN = 1.f / (float)N;
    int nb = (N + 1023) / 1024;

    cudaFuncSetAttribute(gemm_mma<false>,
                         cudaFuncAttributeMaxDynamicSharedMemorySize, SMEM_GEMM);
    cudaFuncSetAttribute(gemm_mma<true>,
                         cudaFuncAttributeMaxDynamicSharedMemorySize, SMEM_GEMM);

    init_kernel<<<(N + 256) / 256, 256>>>((const int*)ei, E, N);
    hist_kernel<<<(E + 255) / 256, 256>>>(ei, E);
    csr_scan<<<nb, 256>>>(N, nb);
    permute_kernel<<<(E + 255) / 256, 256>>>(ei, E);

    int ablocks = (N * 32 + 255) / 256;
    aggregate_kernel<<<ablocks, 256>>>(x, eps, N);

    int gblocks = (N + 127) / 128;
    gemm_mma<false><<<gblocks, 256, SMEM_GEMM>>>(W1, b1, nullptr, nullptr,
                                                 nullptr, N, invN);
    gemm_mma<true><<<gblocks, 256, SMEM_GEMM>>>(W2, b2, g1, be1,
                                                out, N, invN);
    bnrelu_kernel<<<592, 256>>>(out, g2, be2, N, invN);
}

// round 10
// speedup vs baseline: 1.6646x; 1.1604x over previous
#include <cuda_runtime.h>
#include <cuda_fp16.h>
#include <cstdint>

// ---------------------------------------------------------------------------
// GIN block. 8-kernel pipeline:
//   init (dtype detect + zero) -> hist -> single-pass lookback scan ->
//   permute -> aggregate (CSR gather, full occupancy) ->
//   gemm1 (mma.sync 3xFP16-split m16n8k16, fused BN1 stats) ->
//   gemm2 (BN1+ReLU folded on load, fused BN2 stats) -> bnrelu.
// R8 lesson: don't fuse the gather into the 1-CTA/SM GEMM.
// R6 lesson: __device__ symbols only from device code.
// ---------------------------------------------------------------------------

#define MAXN 50048
#define MAXE 1600000

__device__ __align__(16) float g_agg[MAXN * 128];
__device__ __align__(16) float g_h1[MAXN * 128];
__device__ float g_stats[512];   // [sum1, sumsq1, sum2, sumsq2] x 128
__device__ int   g_deg[MAXN + 1];
__device__ int   g_off[MAXN + 1];
__device__ int   g_pos[MAXN + 1];
__device__ unsigned long long g_look[64];  // lookback: flag(hi32) | value(lo32)
__device__ int   g_srcsorted[MAXE];
__device__ int   g_is64;

// ---------------------------------------------------------------------------
__global__ void init_kernel(const int* __restrict__ ei32, int E, int N) {
    int i = blockIdx.x * blockDim.x + threadIdx.x;
    if (i <= N) g_deg[i] = 0;
    if (i < 512) g_stats[i] = 0.f;
    if (i < 64) g_look[i] = 0ull;
    if (blockIdx.x == 0) {
        __shared__ int nz;
        if (threadIdx.x == 0) nz = 0;
        __syncthreads();
        int pairs = E < 2048 ? E : 2048;
        int cnt = 0;
        for (int j = threadIdx.x; j < pairs; j += blockDim.x)
            if (ei32[2 * j + 1] != 0) cnt++;
        if (cnt) atomicOr(&nz, 1);
        __syncthreads();
        if (threadIdx.x == 0) g_is64 = (nz == 0) ? 1 : 0;
    }
}

__device__ __forceinline__ int load_idx(const void* ei, long long i) {
    return g_is64 ? (int)((const long long*)ei)[i] : ((const int*)ei)[i];
}

// 2 edges per thread.
__global__ void hist_kernel(const void* __restrict__ ei, int E) {
    int i = (blockIdx.x * blockDim.x + threadIdx.x) * 2;
    if (i < E)     atomicAdd(&g_deg[load_idx(ei, (long long)E + i)], 1);
    if (i + 1 < E) atomicAdd(&g_deg[load_idx(ei, (long long)E + i + 1)], 1);
}

// Single-pass exclusive scan of g_deg via decoupled lookback (nb <= 49).
__global__ void __launch_bounds__(256) csr_scan(int N, int nb) {
    __shared__ int sh[256];
    __shared__ int sbase;
    int b = blockIdx.x, tid = threadIdx.x;
    int i0 = b * 1024 + tid * 4;
    int d0 = 0, d1 = 0, d2 = 0, d3 = 0;
    if (i0 + 0 < N) d0 = g_deg[i0 + 0];
    if (i0 + 1 < N) d1 = g_deg[i0 + 1];
    if (i0 + 2 < N) d2 = g_deg[i0 + 2];
    if (i0 + 3 < N) d3 = g_deg[i0 + 3];
    int tsum = d0 + d1 + d2 + d3;
    sh[tid] = tsum;
    __syncthreads();
    for (int d = 1; d < 256; d <<= 1) {
        int t = (tid >= d) ? sh[tid - d] : 0;
        __syncthreads();
        sh[tid] += t;
        __syncthreads();
    }
    int agg = sh[255];
    if (tid == 0) {
        if (b == 0) {
            atomicExch(&g_look[0], (2ull << 32) | (unsigned)agg);
            sbase = 0;
        } else {
            atomicExch(&g_look[b], (1ull << 32) | (unsigned)agg);
            int ex = 0;
            int i = b - 1;
            while (true) {
                unsigned long long v;
                do { v = atomicAdd(&g_look[i], 0ull); } while ((v >> 32) == 0ull);
                ex += (int)(unsigned)v;
                if ((v >> 32) == 2ull) break;
                --i;
            }
            atomicExch(&g_look[b], (2ull << 32) | (unsigned)(ex + agg));
            sbase = ex;
        }
    }
    __syncthreads();
    int o0 = sbase + sh[tid] - tsum;
    int o1 = o0 + d0, o2 = o1 + d1, o3 = o2 + d2;
    if (i0 + 0 < N) { g_off[i0 + 0] = o0; g_pos[i0 + 0] = o0; }
    if (i0 + 1 < N) { g_off[i0 + 1] = o1; g_pos[i0 + 1] = o1; }
    if (i0 + 2 < N) { g_off[i0 + 2] = o2; g_pos[i0 + 2] = o2; }
    if (i0 + 3 < N) { g_off[i0 + 3] = o3; g_pos[i0 + 3] = o3; }
    if (b == nb - 1 && tid == 255) g_off[N] = sbase + agg;
}

// 2 edges per thread.
__global__ void permute_kernel(const void* __restrict__ ei, int E) {
    int i = (blockIdx.x * blockDim.x + threadIdx.x) * 2;
    if (i < E) {
        int src = load_idx(ei, i);
        int dst = load_idx(ei, (long long)E + i);
        g_srcsorted[atomicAdd(&g_pos[dst], 1)] = src;
    }
    if (i + 1 < E) {
        int src = load_idx(ei, i + 1);
        int dst = load_idx(ei, (long long)E + i + 1);
        g_srcsorted[atomicAdd(&g_pos[dst], 1)] = src;
    }
}

// One warp per node: acc = (1+eps)*x[node] + sum of neighbor rows; one store.
__global__ void aggregate_kernel(const float* __restrict__ x,
                                 const float* __restrict__ eps, int N) {
    int w = (int)((blockIdx.x * blockDim.x + threadIdx.x) >> 5);
    if (w >= N) return;
    int lane = threadIdx.x & 31;
    const float4* x4 = (const float4*)x;
    float s = 1.f + eps[0];
    float4 acc = x4[(size_t)w * 32 + lane];
    acc.x *= s; acc.y *= s; acc.z *= s; acc.w *= s;
    float4 acc2 = make_float4(0.f, 0.f, 0.f, 0.f);
    int j = g_off[w], end = g_off[w + 1];
    for (; j + 3 < end; j += 4) {
        int s0 = g_srcsorted[j + 0];
        int s1 = g_srcsorted[j + 1];
        int s2 = g_srcsorted[j + 2];
        int s3 = g_srcsorted[j + 3];
        float4 v0 = x4[(size_t)s0 * 32 + lane];
        float4 v1 = x4[(size_t)s1 * 32 + lane];
        float4 v2 = x4[(size_t)s2 * 32 + lane];
        float4 v3 = x4[(size_t)s3 * 32 + lane];
        acc.x  += v0.x + v1.x; acc.y  += v0.y + v1.y;
        acc.z  += v0.z + v1.z; acc.w  += v0.w + v1.w;
        acc2.x += v2.x + v3.x; acc2.y += v2.y + v3.y;
        acc2.z += v2.z + v3.z; acc2.w += v2.w + v3.w;
    }
    for (; j < end; j++) {
        float4 v0 = x4[(size_t)g_srcsorted[j] * 32 + lane];
        acc.x += v0.x; acc.y += v0.y; acc.z += v0.z; acc.w += v0.w;
    }
    acc.x += acc2.x; acc.y += acc2.y; acc.z += acc2.z; acc.w += acc2.w;
    ((float4*)g_agg)[(size_t)w * 32 + lane] = acc;
}

// ---------------------------------------------------------------------------
// 3xFP16-split tensor-core GEMM (m16n8k16): D = Ain @ W^T + bias.
// x = hi + lo (fp16 each, ~22-bit combined mantissa); D accumulates
// Ahi*Bhi + Ahi*Blo + Alo*Bhi in fp32 (lo*lo ~2^-22 dropped).
// SMEM: Ahi/Alo/Bhi/Blo as fp16x2 words [128 rows][68-word stride].
// CTA: 128x128 tile, 8 warps = 4 row-groups(32) x 2 col-groups(64).
// BN1=false (gemm1): A=g_agg, C=g_h1, stats -> g_stats[0/128].
// BN1=true  (gemm2): A=relu(BN1(g_h1)), C=outp, stats -> g_stats[256/384].
// ---------------------------------------------------------------------------
#define ROWW 68                         // words per row (64 + 4 pad)
#define SMO_AH   0
#define SMO_AL   (128*ROWW*4)           // 34816
#define SMO_BH   (2*128*ROWW*4)         // 69632
#define SMO_BL   (3*128*ROWW*4)         // 104448
#define SMO_BIAS (4*128*ROWW*4)         // 139264
#define SMO_SA   (SMO_BIAS + 512)
#define SMO_SC   (SMO_SA + 512)
#define SMO_SS   (SMO_SC + 512)
#define SMO_SQ   (SMO_SS + 512)
#define SMEM_GEMM (SMO_SQ + 512)        // 141824 bytes

__device__ __forceinline__ void split_h2(float x, float y,
                                         uint32_t& hi, uint32_t& lo) {
    __half hx = __float2half_rn(x), hy = __float2half_rn(y);
    __half lx = __float2half_rn(x - __half2float(hx));
    __half ly = __float2half_rn(y - __half2float(hy));
    hi = (uint32_t)__half_as_ushort(hx) | ((uint32_t)__half_as_ushort(hy) << 16);
    lo = (uint32_t)__half_as_ushort(lx) | ((uint32_t)__half_as_ushort(ly) << 16);
}

__device__ __forceinline__ void mma_f16(float* d, const uint32_t* a,
                                        uint32_t b0, uint32_t b1) {
    asm volatile(
        "mma.sync.aligned.m16n8k16.row.col.f32.f16.f16.f32 "
        "{%0,%1,%2,%3}, {%4,%5,%6,%7}, {%8,%9}, {%0,%1,%2,%3};"
        : "+f"(d[0]), "+f"(d[1]), "+f"(d[2]), "+f"(d[3])
        : "r"(a[0]), "r"(a[1]), "r"(a[2]), "r"(a[3]), "r"(b0), "r"(b1));
}

template <bool BN1>
__global__ void __launch_bounds__(256, 1)
gemm_mma(const float* __restrict__ W, const float* __restrict__ bias,
         const float* __restrict__ gamma, const float* __restrict__ beta,
         float* __restrict__ outp, int N, float invN) {
    const float* A  = BN1 ? g_h1 : g_agg;
    float* C        = BN1 ? outp : g_h1;
    float* statSum  = BN1 ? (g_stats + 256) : g_stats;
    float* statSq   = BN1 ? (g_stats + 384) : (g_stats + 128);

    extern __shared__ __align__(16) char smem[];
    uint32_t* Ah = (uint32_t*)(smem + SMO_AH);
    uint32_t* Al = (uint32_t*)(smem + SMO_AL);
    uint32_t* Bh = (uint32_t*)(smem + SMO_BH);
    uint32_t* Bl = (uint32_t*)(smem + SMO_BL);
    float* sbias = (float*)(smem + SMO_BIAS);
    float* s_a   = (float*)(smem + SMO_SA);
    float* s_c   = (float*)(smem + SMO_SC);
    float* sS    = (float*)(smem + SMO_SS);
    float* sQ    = (float*)(smem + SMO_SQ);

    int tid = threadIdx.x, wid = tid >> 5, lane = tid & 31;
    int wr = wid >> 1;        // 0..3 : rows wr*32 .. +32
    int wc = wid & 1;         // 0..1 : cols wc*64 .. +64
    int gid = lane >> 2;      // 0..7
    int tig = lane & 3;       // 0..3
    int m0 = blockIdx.x * 128;

    if (tid < 128) {
        sbias[tid] = bias[tid];
        sS[tid] = 0.f;
        sQ[tid] = 0.f;
        if (BN1) {
            float mu  = g_stats[tid] * invN;
            float var = g_stats[128 + tid] * invN - mu * mu;
            float a = gamma[tid] * rsqrtf(var + 1e-5f);
            s_a[tid] = a;
            s_c[tid] = beta[tid] - mu * a;
        }
    }
    __syncthreads();

    // ---- load + split A tile ----
#pragma unroll
    for (int it = 0; it < 16; ++it) {
        int idx = tid + it * 256;        // 0..4095
        int row = idx >> 5;              // 0..127
        int kq  = idx & 31;              // float4 index 0..31
        int gm = m0 + row; if (gm >= N) gm = N - 1;
        float4 v = *(const float4*)(A + (size_t)gm * 128 + kq * 4);
        if (BN1) {
            int k0 = kq * 4;
            v.x = fmaxf(fmaf(v.x, s_a[k0 + 0], s_c[k0 + 0]), 0.f);
            v.y = fmaxf(fmaf(v.y, s_a[k0 + 1], s_c[k0 + 1]), 0.f);
            v.z = fmaxf(fmaf(v.z, s_a[k0 + 2], s_c[k0 + 2]), 0.f);
            v.w = fmaxf(fmaf(v.w, s_a[k0 + 3], s_c[k0 + 3]), 0.f);
        }
        uint32_t h0, l0, h1, l1;
        split_h2(v.x, v.y, h0, l0);
        split_h2(v.z, v.w, h1, l1);
        int o = row * ROWW + kq * 2;
        *(uint2*)(Ah + o) = make_uint2(h0, h1);
        *(uint2*)(Al + o) = make_uint2(l0, l1);
    }
    // ---- load + split W ----
#pragma unroll
    for (int it = 0; it < 16; ++it) {
        int idx = tid + it * 256;
        int row = idx >> 5;              // n
        int kq  = idx & 31;
        float4 v = *(const float4*)(W + (size_t)row * 128 + kq * 4);
        uint32_t h0, l0, h1, l1;
        split_h2(v.x, v.y, h0, l0);
        split_h2(v.z, v.w, h1, l1);
        int o = row * ROWW + kq * 2;
        *(uint2*)(Bh + o) = make_uint2(h0, h1);
        *(uint2*)(Bl + o) = make_uint2(l0, l1);
    }
    __syncthreads();

    // ---- mainloop: 8 K-chunks of 16 ----
    float acc[2][8][4];
#pragma unroll
    for (int mt = 0; mt < 2; ++mt)
#pragma unroll
        for (int nt = 0; nt < 8; ++nt)
#pragma unroll
            for (int r = 0; r < 4; ++r) acc[mt][nt][r] = 0.f;

#pragma unroll
    for (int ks = 0; ks < 8; ++ks) {
        int kw0 = ks * 8;  // word offset of this K-chunk
        uint32_t ahi[2][4], alo[2][4];
#pragma unroll
        for (int mt = 0; mt < 2; ++mt) {
            int r0 = wr * 32 + mt * 16 + gid;
            ahi[mt][0] = Ah[r0 * ROWW + kw0 + tig];
            ahi[mt][1] = Ah[(r0 + 8) * ROWW + kw0 + tig];
            ahi[mt][2] = Ah[r0 * ROWW + kw0 + tig + 4];
            ahi[mt][3] = Ah[(r0 + 8) * ROWW + kw0 + tig + 4];
            alo[mt][0] = Al[r0 * ROWW + kw0 + tig];
            alo[mt][1] = Al[(r0 + 8) * ROWW + kw0 + tig];
            alo[mt][2] = Al[r0 * ROWW + kw0 + tig + 4];
            alo[mt][3] = Al[(r0 + 8) * ROWW + kw0 + tig + 4];
        }
#pragma unroll
        for (int nt = 0; nt < 8; ++nt) {
            int n = wc * 64 + nt * 8 + gid;
            uint32_t bh0 = Bh[n * ROWW + kw0 + tig];
            uint32_t bh1 = Bh[n * ROWW + kw0 + tig + 4];
            uint32_t bl0 = Bl[n * ROWW + kw0 + tig];
            uint32_t bl1 = Bl[n * ROWW + kw0 + tig + 4];
#pragma unroll
            for (int mt = 0; mt < 2; ++mt) {
                mma_f16(acc[mt][nt], ahi[mt], bh0, bh1);
                mma_f16(acc[mt][nt], ahi[mt], bl0, bl1);
                mma_f16(acc[mt][nt], alo[mt], bh0, bh1);
            }
        }
    }

    // ---- epilogue: bias add, store, fused column stats ----
    float ls[16], lq[16];
#pragma unroll
    for (int i = 0; i < 16; ++i) { ls[i] = 0.f; lq[i] = 0.f; }

#pragma unroll
    for (int mt = 0; mt < 2; ++mt) {
        int grow0 = m0 + wr * 32 + mt * 16 + gid;
        int grow1 = grow0 + 8;
        bool v0 = grow0 < N, v1 = grow1 < N;
#pragma unroll
        for (int nt = 0; nt < 8; ++nt) {
            int gcol = wc * 64 + nt * 8 + tig * 2;
            float d0 = acc[mt][nt][0] + sbias[gcol];
            float d1 = acc[mt][nt][1] + sbias[gcol + 1];
            float d2 = acc[mt][nt][2] + sbias[gcol];
            float d3 = acc[mt][nt][3] + sbias[gcol + 1];
            if (v0) {
                *(float2*)(C + (size_t)grow0 * 128 + gcol) = make_float2(d0, d1);
                ls[nt * 2]     += d0; lq[nt * 2]     = fmaf(d0, d0, lq[nt * 2]);
                ls[nt * 2 + 1] += d1; lq[nt * 2 + 1] = fmaf(d1, d1, lq[nt * 2 + 1]);
            }
            if (v1) {
                *(float2*)(C + (size_t)grow1 * 128 + gcol) = make_float2(d2, d3);
                ls[nt * 2]     += d2; lq[nt * 2]     = fmaf(d2, d2, lq[nt * 2]);
                ls[nt * 2 + 1] += d3; lq[nt * 2 + 1] = fmaf(d3, d3, lq[nt * 2 + 1]);
            }
        }
    }
#pragma unroll
    for (int d = 4; d < 32; d <<= 1) {
#pragma unroll
        for (int i = 0; i < 16; ++i) {
            ls[i] += __shfl_xor_sync(0xFFFFFFFFu, ls[i], d);
            lq[i] += __shfl_xor_sync(0xFFFFFFFFu, lq[i], d);
        }
    }
    if (gid == 0) {
#pragma unroll
        for (int i = 0; i < 16; ++i) {
            int col = wc * 64 + (i >> 1) * 8 + tig * 2 + (i & 1);
            atomicAdd(&sS[col], ls[i]);
            atomicAdd(&sQ[col], lq[i]);
        }
    }
    __syncthreads();
    if (tid < 128) {
        atomicAdd(&statSum[tid], sS[tid]);
        atomicAdd(&statSq[tid],  sQ[tid]);
    }
}

// out = relu(BN2(out)), BN2 affine computed per block from g_stats.
__global__ void __launch_bounds__(256)
bnrelu_kernel(float* __restrict__ out,
              const float* __restrict__ gamma, const float* __restrict__ beta,
              int N, float invN) {
    __shared__ float s_a[128], s_c[128];
    int tid = threadIdx.x;
    if (tid < 128) {
        float mu  = g_stats[256 + tid] * invN;
        float var = g_stats[384 + tid] * invN - mu * mu;
        float a = gamma[tid] * rsqrtf(var + 1e-5f);
        s_a[tid] = a;
        s_c[tid] = beta[tid] - mu * a;
    }
    __syncthreads();
    int c4 = (tid & 31) << 2;
    float4 a4  = *(const float4*)(s_a + c4);
    float4 c4v = *(const float4*)(s_c + c4);
    int rows_per_iter = gridDim.x * (blockDim.x >> 5);
    int r = blockIdx.x * (blockDim.x >> 5) + (tid >> 5);
    float4* o4 = (float4*)out;
    for (; r < N; r += rows_per_iter) {
        size_t idx = (size_t)r * 32 + (tid & 31);
        float4 v = o4[idx];
        v.x = fmaxf(fmaf(v.x, a4.x, c4v.x), 0.f);
        v.y = fmaxf(fmaf(v.y, a4.y, c4v.y), 0.f);
        v.z = fmaxf(fmaf(v.z, a4.z, c4v.z), 0.f);
        v.w = fmaxf(fmaf(v.w, a4.w, c4v.w), 0.f);
        o4[idx] = v;
    }
}

// ---------------------------------------------------------------------------
extern "C" void kernel_launch(void* const* d_in, const int* in_sizes, int n_in,
                              void* d_out, int out_size) {
    const float* x   = (const float*)d_in[0];
    const void*  ei  = d_in[1];
    const float* eps = (const float*)d_in[2];
    const float* W1  = (const float*)d_in[3];
    const float* b1  = (const float*)d_in[4];
    const float* g1  = (const float*)d_in[5];
    const float* be1 = (const float*)d_in[6];
    const float* W2  = (const float*)d_in[7];
    const float* b2  = (const float*)d_in[8];
    const float* g2  = (const float*)d_in[9];
    const float* be2 = (const float*)d_in[10];

    int N = in_sizes[0] / 128;
    int E = in_sizes[1] / 2;
    if (E > MAXE) E = MAXE;
    float* out = (float*)d_out;
    float invN = 1.f / (float)N;
    int nb = (N + 1023) / 1024;

    cudaFuncSetAttribute(gemm_mma<false>,
                         cudaFuncAttributeMaxDynamicSharedMemorySize, SMEM_GEMM);
    cudaFuncSetAttribute(gemm_mma<true>,
                         cudaFuncAttributeMaxDynamicSharedMemorySize, SMEM_GEMM);

    init_kernel<<<(N + 256) / 256, 256>>>((const int*)ei, E, N);
    hist_kernel<<<(E + 511) / 512, 256>>>(ei, E);
    csr_scan<<<nb, 256>>>(N, nb);
    permute_kernel<<<(E + 511) / 512, 256>>>(ei, E);

    int ablocks = (N * 32 + 255) / 256;
    aggregate_kernel<<<ablocks, 256>>>(x, eps, N);

    int gblocks = (N + 127) / 128;
    gemm_mma<false><<<gblocks, 256, SMEM_GEMM>>>(W1, b1, nullptr, nullptr,
                                                 nullptr, N, invN);
    gemm_mma<true><<<gblocks, 256, SMEM_GEMM>>>(W2, b2, g1, be1,
                                                out, N, invN);
    bnrelu_kernel<<<592, 256>>>(out, g2, be2, N, invN);
}